// round 16
// baseline (speedup 1.0000x reference)
#include <cuda_runtime.h>
#include <cuda_bf16.h>
#include <stdint.h>
#include <math.h>

#define BATCH 32
#define NDIM  325
#define T1D   288
#define T3D   864
#define TLEN  2016
#define KSZ   577
#define FREQ  513
#define LFFT  1024
#define FEAT  (BATCH*T3D*NDIM)
#define MROWS (BATCH*T3D)
#define KP    384
#define NW    (NDIM*NDIM)
#define NG    (BATCH*NDIM)
#define IPAD  336
#define OPAD  384

// ---------------- static device scratch ----------------
__device__ float  g_buf0[FEAT];
__device__ float  g_buf1[FEAT];
__device__ float  g_s1[FEAT];
__device__ float  g_s2[FEAT];
__device__ __nv_bfloat16 g_ah0[(size_t)MROWS*KP];
__device__ __nv_bfloat16 g_al0[(size_t)MROWS*KP];
__device__ __nv_bfloat16 g_ah1[(size_t)MROWS*KP];
__device__ __nv_bfloat16 g_al1[(size_t)MROWS*KP];
__device__ __nv_bfloat16 g_wth[6*KP*KP];
__device__ __nv_bfloat16 g_wtl[6*KP*KP];
__device__ float2 g_ghat[(size_t)NG*FREQ];
__device__ float2 g_what[(size_t)NW*FREQ];
__device__ float2 g_ohat[(size_t)NG*FREQ];
__device__ float2 g_twf[LFFT];
__device__ float2 g_twi[LFFT];
// bf16 split planes for tensor-core fgemm
__device__ __nv_bfloat16 g_wprh[(size_t)FREQ*OPAD*IPAD];
__device__ __nv_bfloat16 g_wprl[(size_t)FREQ*OPAD*IPAD];
__device__ __nv_bfloat16 g_wpih[(size_t)FREQ*OPAD*IPAD];
__device__ __nv_bfloat16 g_wpil[(size_t)FREQ*OPAD*IPAD];
__device__ __nv_bfloat16 g_gprh[(size_t)FREQ*32*IPAD];
__device__ __nv_bfloat16 g_gprl[(size_t)FREQ*32*IPAD];
__device__ __nv_bfloat16 g_gpih[(size_t)FREQ*32*IPAD];
__device__ __nv_bfloat16 g_gpil[(size_t)FREQ*32*IPAD];
__device__ __nv_bfloat16 g_gnrh[(size_t)FREQ*32*IPAD];
__device__ __nv_bfloat16 g_gnrl[(size_t)FREQ*32*IPAD];

struct WP4 { __nv_bfloat16 *rh, *rl, *ih, *il; };
struct GP6 { __nv_bfloat16 *rh, *rl, *ih, *il, *nrh, *nrl; };

// ---------------- gather (+bf16 split) ----------------
__global__ void gather_split_kernel(const float* __restrict__ infeat,
                                    const float* __restrict__ x,
                                    const int* __restrict__ week,
                                    const int* __restrict__ hour) {
    int idx = blockIdx.x * blockDim.x + threadIdx.x;
    if (idx >= MROWS * KP) return;
    int d = idx % KP, t = idx / KP;
    int m = t % T3D, b = t / T3D;
    float v = 0.f;
    if (d < NDIM) {
        if (m >= T1D && m < 2 * T1D) {
            v = infeat[(b * NDIM + d) * T1D + (m - T1D)];
        } else {
            int s  = week[b] * T1D + hour[b];
            int tt = (m + s + (TLEN - T1D)) % TLEN;
            v = x[tt * NDIM + d];
        }
    }
    __nv_bfloat16 h = __float2bfloat16(v);
    g_ah0[idx] = h;
    g_al0[idx] = __float2bfloat16(v - __bfloat162float(h));
}

struct W6 { const float* p[6]; };
__global__ void wsplit_kernel(W6 wp) {
    int idx = blockIdx.x * blockDim.x + threadIdx.x;
    if (idx >= 6 * KP * KP) return;
    int g = idx / (KP * KP);
    int r = idx - g * KP * KP;
    int n = r / KP, k = r - n * KP;
    float v = (n < NDIM && k < NDIM) ? wp.p[g][k * NDIM + n] : 0.f;
    __nv_bfloat16 h = __float2bfloat16(v);
    g_wth[idx] = h;
    g_wtl[idx] = __float2bfloat16(v - __bfloat162float(h));
}

// ---------------- split-bf16 mma.sync GEMM (proven R11) ----------------
#define SMS    72
#define OFF_AH 0
#define OFF_AL (128*SMS*2)
#define OFF_BH (2*128*SMS*2)
#define OFF_BL (2*128*SMS*2 + 64*SMS*2)
#define MMA_SMEM (2*128*SMS*2 + 2*64*SMS*2)

#define MMA16816(c, a, b) \
    asm volatile("mma.sync.aligned.m16n8k16.row.col.f32.bf16.bf16.f32 " \
        "{%0,%1,%2,%3}, {%4,%5,%6,%7}, {%8,%9}, {%0,%1,%2,%3};" \
        : "+f"((c)[0]), "+f"((c)[1]), "+f"((c)[2]), "+f"((c)[3]) \
        : "r"((a)[0]), "r"((a)[1]), "r"((a)[2]), "r"((a)[3]), "r"((b)[0]), "r"((b)[1]))

__global__ __launch_bounds__(256)
void gemm_mma(const __nv_bfloat16* __restrict__ Ah, const __nv_bfloat16* __restrict__ Al,
              const __nv_bfloat16* __restrict__ Bh, const __nv_bfloat16* __restrict__ Bl,
              float* __restrict__ C) {
    extern __shared__ char smem[];
    __nv_bfloat16* sAh = (__nv_bfloat16*)(smem + OFF_AH);
    __nv_bfloat16* sAl = (__nv_bfloat16*)(smem + OFF_AL);
    __nv_bfloat16* sBh = (__nv_bfloat16*)(smem + OFF_BH);
    __nv_bfloat16* sBl = (__nv_bfloat16*)(smem + OFF_BL);
    int tid = threadIdx.x, wid = tid >> 5, lane = tid & 31;
    int bm = blockIdx.x * 128, n0 = blockIdx.y * 64;
    int wrow = (wid >> 1) * 32, wcol = (wid & 1) * 32;
    int lr = lane >> 2;
    int lc = (lane & 3) * 2;

    float acc[2][4][4];
#pragma unroll
    for (int mt = 0; mt < 2; mt++)
#pragma unroll
        for (int nt = 0; nt < 4; nt++)
#pragma unroll
            for (int q = 0; q < 4; q++) acc[mt][nt][q] = 0.f;

    for (int k0 = 0; k0 < KP; k0 += 64) {
        __syncthreads();
        for (int i = tid; i < 1024; i += 256) {
            int r = i >> 3, q = i & 3, half = (i >> 2) & 1;
            int qq = half * 4 + q;
            *(uint4*)(sAh + r * SMS + qq * 8) =
                *(const uint4*)(Ah + (size_t)(bm + r) * KP + k0 + qq * 8);
            *(uint4*)(sAl + r * SMS + qq * 8) =
                *(const uint4*)(Al + (size_t)(bm + r) * KP + k0 + qq * 8);
        }
        for (int i = tid; i < 512; i += 256) {
            int r = i >> 3, qq = i & 7;
            *(uint4*)(sBh + r * SMS + qq * 8) =
                *(const uint4*)(Bh + (size_t)(n0 + r) * KP + k0 + qq * 8);
            *(uint4*)(sBl + r * SMS + qq * 8) =
                *(const uint4*)(Bl + (size_t)(n0 + r) * KP + k0 + qq * 8);
        }
        __syncthreads();

#pragma unroll
        for (int ks = 0; ks < 4; ks++) {
            int kk = ks * 16;
            uint32_t ah[2][4], al[2][4], bh[4][2], bl[4][2];
#pragma unroll
            for (int mt = 0; mt < 2; mt++) {
                int r = wrow + mt * 16 + lr;
                ah[mt][0] = *(const uint32_t*)(sAh + r * SMS + kk + lc);
                ah[mt][1] = *(const uint32_t*)(sAh + (r + 8) * SMS + kk + lc);
                ah[mt][2] = *(const uint32_t*)(sAh + r * SMS + kk + lc + 8);
                ah[mt][3] = *(const uint32_t*)(sAh + (r + 8) * SMS + kk + lc + 8);
                al[mt][0] = *(const uint32_t*)(sAl + r * SMS + kk + lc);
                al[mt][1] = *(const uint32_t*)(sAl + (r + 8) * SMS + kk + lc);
                al[mt][2] = *(const uint32_t*)(sAl + r * SMS + kk + lc + 8);
                al[mt][3] = *(const uint32_t*)(sAl + (r + 8) * SMS + kk + lc + 8);
            }
#pragma unroll
            for (int nt = 0; nt < 4; nt++) {
                int n = wcol + nt * 8 + lr;
                bh[nt][0] = *(const uint32_t*)(sBh + n * SMS + kk + lc);
                bh[nt][1] = *(const uint32_t*)(sBh + n * SMS + kk + lc + 8);
                bl[nt][0] = *(const uint32_t*)(sBl + n * SMS + kk + lc);
                bl[nt][1] = *(const uint32_t*)(sBl + n * SMS + kk + lc + 8);
            }
#pragma unroll
            for (int mt = 0; mt < 2; mt++)
#pragma unroll
                for (int nt = 0; nt < 4; nt++) {
                    MMA16816(acc[mt][nt], ah[mt], bh[nt]);
                    MMA16816(acc[mt][nt], ah[mt], bl[nt]);
                    MMA16816(acc[mt][nt], al[mt], bh[nt]);
                }
        }
    }

#pragma unroll
    for (int mt = 0; mt < 2; mt++) {
        size_t row = (size_t)bm + wrow + mt * 16 + lr;
#pragma unroll
        for (int nt = 0; nt < 4; nt++) {
            int col = n0 + wcol + nt * 8 + lc;
            if (col < NDIM)     C[row * NDIM + col]           = acc[mt][nt][0];
            if (col + 1 < NDIM) C[row * NDIM + col + 1]       = acc[mt][nt][1];
            if (col < NDIM)     C[(row + 8) * NDIM + col]     = acc[mt][nt][2];
            if (col + 1 < NDIM) C[(row + 8) * NDIM + col + 1] = acc[mt][nt][3];
        }
    }
}

// ---------------- banded-A stencil + gate (+bf16 split) ----------------
__global__ void stencil_split_kernel(const float* __restrict__ S1, const float* __restrict__ S2,
                                     const float* __restrict__ bt, const float* __restrict__ bs,
                                     float* __restrict__ outp,
                                     __nv_bfloat16* __restrict__ oh, __nv_bfloat16* __restrict__ ol) {
    int idx = blockIdx.x * blockDim.x + threadIdx.x;
    if (idx >= MROWS * KP) return;
    int o = idx % KP, bm = idx / KP;
    float val = 0.f;
    if (o < NDIM) {
        int m = bm % T3D;
        size_t base = (size_t)(bm - m) * NDIM + o;
        float dm = rsqrtf((float)(1 + min(m, 3) + min(T3D - 1 - m, 3)));
        int lo = (m > 3) ? m - 3 : 0;
        int hi = (m < T3D - 4) ? m + 3 : T3D - 1;
        float s1 = 0.f, s2 = 0.f;
        for (int n = lo; n <= hi; n++) {
            float dn = rsqrtf((float)(1 + min(n, 3) + min(T3D - 1 - n, 3)));
            float w = dm * dn;
            s1 += w * S1[base + (size_t)n * NDIM];
            s2 += w * S2[base + (size_t)n * NDIM];
        }
        float gv = tanhf(s1 + bt[o]);
        float sv = 1.f / (1.f + expf(-(s2 + bs[o])));
        val = gv * sv;
        outp[(size_t)bm * NDIM + o] = val;
    }
    __nv_bfloat16 h = __float2bfloat16(val);
    oh[idx] = h;
    ol[idx] = __float2bfloat16(val - __bfloat162float(h));
}

// ---------------- FFT: radix-4 Stockham, real-pair packed (proven R15) ----------------
__global__ void init_tw_kernel() {
    int idx = blockIdx.x * blockDim.x + threadIdx.x;
    if (idx >= LFFT) return;
    if (idx == 0) { g_twf[0] = make_float2(1.f,0.f); g_twi[0] = make_float2(1.f,0.f); return; }
    int Ns = 1 << (31 - __clz(idx));
    float ang = 3.14159265358979323846f * (float)(idx - Ns) / (float)Ns;
    float s, c; sincosf(ang, &s, &c);
    g_twf[idx] = make_float2(c, -s);
    g_twi[idx] = make_float2(c,  s);
}

__device__ __forceinline__ float2 cmul(float2 a, float2 b) {
    return make_float2(a.x*b.x - a.y*b.y, a.x*b.y + a.y*b.x);
}

template<int INV>
__device__ __forceinline__ float2* fft1024_r4(float2* a, float2* b, const float2* tw) {
    int tid = threadIdx.x;
    float2 *src = a, *dst = b;
#pragma unroll
    for (int Ns = 1; Ns < LFFT; Ns <<= 2) {
        int r = tid & (Ns - 1);
        float2 a0 = src[tid];
        float2 a1 = src[tid + 256];
        float2 a2 = src[tid + 512];
        float2 a3 = src[tid + 768];
        float2 w1 = tw[2 * Ns + r];
        float2 w2 = tw[Ns + r];
        float2 w3 = cmul(w1, w2);
        a1 = cmul(a1, w1);
        a2 = cmul(a2, w2);
        a3 = cmul(a3, w3);
        float2 s0 = make_float2(a0.x + a2.x, a0.y + a2.y);
        float2 d0 = make_float2(a0.x - a2.x, a0.y - a2.y);
        float2 s1 = make_float2(a1.x + a3.x, a1.y + a3.y);
        float2 d1 = make_float2(a1.x - a3.x, a1.y - a3.y);
        float2 b0 = make_float2(s0.x + s1.x, s0.y + s1.y);
        float2 b2 = make_float2(s0.x - s1.x, s0.y - s1.y);
        float2 b1, b3;
        if (INV == 0) {
            b1 = make_float2(d0.x + d1.y, d0.y - d1.x);
            b3 = make_float2(d0.x - d1.y, d0.y + d1.x);
        } else {
            b1 = make_float2(d0.x - d1.y, d0.y + d1.x);
            b3 = make_float2(d0.x + d1.y, d0.y - d1.x);
        }
        int oi = ((tid - r) << 2) + r;
        dst[oi]          = b0;
        dst[oi + Ns]     = b1;
        dst[oi + 2*Ns]   = b2;
        dst[oi + 3*Ns]   = b3;
        __syncthreads();
        float2* t2 = src; src = dst; dst = t2;
    }
    return src;
}

__global__ __launch_bounds__(256)
void fft_w_kernel(const float* __restrict__ cw) {
    __shared__ float2 bufA[LFFT], bufB[LFFT], tws[LFFT];
    int tid = threadIdx.x;
    int r0 = blockIdx.x * 2, r1 = r0 + 1;
    bool has1 = (r1 < NW);
    const float* s0 = cw + (size_t)r0 * KSZ;
    const float* s1 = cw + (size_t)r1 * KSZ;
    for (int t = tid; t < LFFT; t += 256) {
        tws[t] = g_twf[t];
        float v0 = (t < KSZ) ? s0[t] : 0.f;
        float v1 = (has1 && t < KSZ) ? s1[t] : 0.f;
        bufA[t] = make_float2(v0, v1);
    }
    __syncthreads();
    float2* res = fft1024_r4<0>(bufA, bufB, tws);
    float2* d0 = g_what + (size_t)r0 * FREQ;
    float2* d1 = g_what + (size_t)r1 * FREQ;
    for (int f = tid; f <= 512; f += 256) {
        int m = (LFFT - f) & (LFFT - 1);
        float2 zf = res[f], zm = res[m];
        d0[f] = make_float2(0.5f * (zf.x + zm.x), 0.5f * (zf.y - zm.y));
        if (has1) d1[f] = make_float2(0.5f * (zf.y + zm.y), -0.5f * (zf.x - zm.x));
    }
}

__global__ __launch_bounds__(256)
void fft_g_kernel(const float* __restrict__ G) {
    __shared__ float2 bufA[LFFT], bufB[LFFT], tws[LFFT];
    int tid = threadIdx.x;
    int r0 = blockIdx.x * 2, r1 = r0 + 1;
    int b0 = r0 / NDIM, i0 = r0 % NDIM;
    int b1 = r1 / NDIM, i1 = r1 % NDIM;
    const float* s0 = G + (size_t)b0 * T3D * NDIM + i0;
    const float* s1 = G + (size_t)b1 * T3D * NDIM + i1;
    for (int t = tid; t < LFFT; t += 256) {
        tws[t] = g_twf[t];
        float v0 = (t < T3D) ? s0[(size_t)t * NDIM] : 0.f;
        float v1 = (t < T3D) ? s1[(size_t)t * NDIM] : 0.f;
        bufA[t] = make_float2(v0, v1);
    }
    __syncthreads();
    float2* res = fft1024_r4<0>(bufA, bufB, tws);
    float2* d0 = g_ghat + (size_t)r0 * FREQ;
    float2* d1 = g_ghat + (size_t)r1 * FREQ;
    for (int f = tid; f <= 512; f += 256) {
        int m = (LFFT - f) & (LFFT - 1);
        float2 zf = res[f], zm = res[m];
        d0[f] = make_float2(0.5f * (zf.x + zm.x), 0.5f * (zf.y - zm.y));
        d1[f] = make_float2(0.5f * (zf.y + zm.y), -0.5f * (zf.x - zm.x));
    }
}

// ---------------- repack What/Ghat to bf16 split planes [f][o/b][iPad] ----------------
__global__ __launch_bounds__(256)
void wrepack_kernel(WP4 wp) {
    __shared__ float2 t[32][33];
    int oi0 = blockIdx.x * 32, f0 = blockIdx.y * 32;
    int tid = threadIdx.x;
    for (int i = tid; i < 1024; i += 256) {
        int r = i >> 5, c = i & 31;
        int oi = oi0 + r, f = f0 + c;
        float2 v = make_float2(0.f, 0.f);
        if (oi < NW && f < FREQ) v = g_what[(size_t)oi * FREQ + f];
        t[r][c] = v;
    }
    __syncthreads();
    for (int i = tid; i < 1024; i += 256) {
        int fr = i >> 5, c = i & 31;
        int f = f0 + fr, oi = oi0 + c;
        if (f >= FREQ || oi >= NW) continue;
        float2 v = t[c][fr];
        int o = oi / NDIM, ii = oi - o * NDIM;
        size_t ad = (size_t)f * (OPAD * IPAD) + (size_t)o * IPAD + ii;
        __nv_bfloat16 h;
        h = __float2bfloat16(v.x); wp.rh[ad] = h; wp.rl[ad] = __float2bfloat16(v.x - __bfloat162float(h));
        h = __float2bfloat16(v.y); wp.ih[ad] = h; wp.il[ad] = __float2bfloat16(v.y - __bfloat162float(h));
    }
}

__global__ __launch_bounds__(256)
void grepack_kernel(GP6 gp) {
    __shared__ float2 t[32][33];
    int bi0 = blockIdx.x * 32, f0 = blockIdx.y * 32;
    int tid = threadIdx.x;
    for (int i = tid; i < 1024; i += 256) {
        int r = i >> 5, c = i & 31;
        int bi = bi0 + r, f = f0 + c;
        float2 v = make_float2(0.f, 0.f);
        if (bi < NG && f < FREQ) v = g_ghat[(size_t)bi * FREQ + f];
        t[r][c] = v;
    }
    __syncthreads();
    for (int i = tid; i < 1024; i += 256) {
        int fr = i >> 5, c = i & 31;
        int f = f0 + fr, bi = bi0 + c;
        if (f >= FREQ || bi >= NG) continue;
        float2 v = t[c][fr];
        int b = bi / NDIM, ii = bi - b * NDIM;
        size_t ad = (size_t)f * (32 * IPAD) + (size_t)b * IPAD + ii;
        __nv_bfloat16 h, l;
        h = __float2bfloat16(v.x); l = __float2bfloat16(v.x - __bfloat162float(h));
        gp.rh[ad] = h; gp.rl[ad] = l;
        gp.nrh[ad] = __float2bfloat16(-__bfloat162float(h));
        gp.nrl[ad] = __float2bfloat16(-__bfloat162float(l));
        h = __float2bfloat16(v.y); gp.ih[ad] = h; gp.il[ad] = __float2bfloat16(v.y - __bfloat162float(h));
    }
}

// zero the pad regions (must run every launch; graph-replayed)
__global__ void zpadw_kernel(WP4 wp) {
    long long idx = (long long)blockIdx.x * blockDim.x + threadIdx.x;
    const int PER_F = 59 * 336 + 325 * 11;   // 23399
    if (idx >= (long long)FREQ * PER_F) return;
    int f = (int)(idx / PER_F);
    int rem = (int)(idx % PER_F);
    int o, ii;
    if (rem < 59 * 336) { o = 325 + rem / 336; ii = rem % 336; }
    else { int r2 = rem - 59 * 336; o = r2 / 11; ii = 325 + r2 % 11; }
    size_t ad = (size_t)f * (OPAD * IPAD) + (size_t)o * IPAD + ii;
    __nv_bfloat16 z = __float2bfloat16(0.f);
    wp.rh[ad] = z; wp.rl[ad] = z; wp.ih[ad] = z; wp.il[ad] = z;
}

__global__ void zpadg_kernel(GP6 gp) {
    int idx = blockIdx.x * blockDim.x + threadIdx.x;
    if (idx >= FREQ * 32 * 11) return;
    int f = idx / 352, rem = idx % 352;
    int b = rem / 11, ii = 325 + rem % 11;
    size_t ad = (size_t)f * (32 * IPAD) + (size_t)b * IPAD + ii;
    __nv_bfloat16 z = __float2bfloat16(0.f);
    gp.rh[ad] = z; gp.rl[ad] = z; gp.ih[ad] = z; gp.il[ad] = z; gp.nrh[ad] = z; gp.nrl[ad] = z;
}

// ---------------- tensor-core frequency GEMM ----------------
// Ohat[b,o,f] = sum_i Ghat[b,i,f]*conj(What[o,i,f]);
// Or = Gr*Wr + Gi*Wi ; Oi = Gi*Wr + (-Gr)*Wi ; each with 3-product bf16 split.
#define FG_SMEM 50176
__global__ __launch_bounds__(256)
void fgemm_mma(GP6 gp, WP4 wpp) {
    extern __shared__ __nv_bfloat16 sm[];
    // G planes at p*1792 (stride 56, 32 rows); W planes at 10752 + p*3584 (64 rows)
    int tid = threadIdx.x, wid = tid >> 5, lane = tid & 31;
    int f = blockIdx.x, o0 = blockIdx.y * 64;
    int wrow = (wid & 1) * 16, wcol = (wid >> 1) * 16;
    int lr = lane >> 2, lc = (lane & 3) * 2;

    float or_[2][4], oi_[2][4];
#pragma unroll
    for (int p = 0; p < 2; p++)
#pragma unroll
        for (int q = 0; q < 4; q++) { or_[p][q] = 0.f; oi_[p][q] = 0.f; }

    const __nv_bfloat16* gsrc[6] = {gp.rh, gp.rl, gp.ih, gp.il, gp.nrh, gp.nrl};
    const __nv_bfloat16* wsrc[4] = {wpp.rh, wpp.rl, wpp.ih, wpp.il};

    for (int kc = 0; kc < 7; kc++) {
        __syncthreads();
        if (tid < 192) {
            int r = tid / 6, q = tid % 6;
            size_t so = (size_t)f * (32 * IPAD) + (size_t)r * IPAD + kc * 48 + q * 8;
#pragma unroll
            for (int p = 0; p < 6; p++)
                *(uint4*)(sm + p * 1792 + r * 56 + q * 8) = *(const uint4*)(gsrc[p] + so);
        }
        for (int i = tid; i < 384; i += 256) {
            int r = i / 6, q = i % 6;
            size_t so = (size_t)f * (OPAD * IPAD) + (size_t)(o0 + r) * IPAD + kc * 48 + q * 8;
#pragma unroll
            for (int p = 0; p < 4; p++)
                *(uint4*)(sm + 10752 + p * 3584 + r * 56 + q * 8) = *(const uint4*)(wsrc[p] + so);
        }
        __syncthreads();

#pragma unroll
        for (int ks = 0; ks < 3; ks++) {
            int kk = ks * 16;
            uint32_t a[6][4];
#pragma unroll
            for (int p = 0; p < 6; p++) {
                const __nv_bfloat16* base = sm + p * 1792;
                int r = wrow + lr;
                a[p][0] = *(const uint32_t*)(base + r * 56 + kk + lc);
                a[p][1] = *(const uint32_t*)(base + (r + 8) * 56 + kk + lc);
                a[p][2] = *(const uint32_t*)(base + r * 56 + kk + lc + 8);
                a[p][3] = *(const uint32_t*)(base + (r + 8) * 56 + kk + lc + 8);
            }
            uint32_t bf[4][2][2];
#pragma unroll
            for (int p = 0; p < 4; p++)
#pragma unroll
                for (int np = 0; np < 2; np++) {
                    const __nv_bfloat16* base = sm + 10752 + p * 3584;
                    int n = wcol + np * 8 + lr;
                    bf[p][np][0] = *(const uint32_t*)(base + n * 56 + kk + lc);
                    bf[p][np][1] = *(const uint32_t*)(base + n * 56 + kk + lc + 8);
                }
#pragma unroll
            for (int np = 0; np < 2; np++) {
                MMA16816(or_[np], a[0], bf[0][np]);   // Grh*Wrh
                MMA16816(or_[np], a[0], bf[1][np]);   // Grh*Wrl
                MMA16816(or_[np], a[1], bf[0][np]);   // Grl*Wrh
                MMA16816(or_[np], a[2], bf[2][np]);   // Gih*Wih
                MMA16816(or_[np], a[2], bf[3][np]);   // Gih*Wil
                MMA16816(or_[np], a[3], bf[2][np]);   // Gil*Wih
                MMA16816(oi_[np], a[2], bf[0][np]);   // Gih*Wrh
                MMA16816(oi_[np], a[2], bf[1][np]);   // Gih*Wrl
                MMA16816(oi_[np], a[3], bf[0][np]);   // Gil*Wrh
                MMA16816(oi_[np], a[4], bf[2][np]);   // Gnrh*Wih
                MMA16816(oi_[np], a[4], bf[3][np]);   // Gnrh*Wil
                MMA16816(oi_[np], a[5], bf[2][np]);   // Gnrl*Wih
            }
        }
    }

    int b = wrow + lr;
#pragma unroll
    for (int np = 0; np < 2; np++) {
        int o = o0 + wcol + np * 8 + lc;
        if (o < NDIM) {
            g_ohat[((size_t)b * NDIM + o) * FREQ + f]       = make_float2(or_[np][0], oi_[np][0]);
            g_ohat[((size_t)(b + 8) * NDIM + o) * FREQ + f] = make_float2(or_[np][2], oi_[np][2]);
        }
        if (o + 1 < NDIM) {
            g_ohat[((size_t)b * NDIM + o + 1) * FREQ + f]       = make_float2(or_[np][1], oi_[np][1]);
            g_ohat[((size_t)(b + 8) * NDIM + o + 1) * FREQ + f] = make_float2(or_[np][3], oi_[np][3]);
        }
    }
}

// Inverse: two output rows per block.
__global__ __launch_bounds__(256)
void ifft_kernel(const float* __restrict__ cb, float* __restrict__ outp) {
    __shared__ float2 bufA[LFFT], bufB[LFFT], tws[LFFT];
    int tid = threadIdx.x;
    int r0 = blockIdx.x * 2, r1 = r0 + 1;
    const float2* s0 = g_ohat + (size_t)r0 * FREQ;
    const float2* s1 = g_ohat + (size_t)r1 * FREQ;
    for (int f = tid; f < LFFT; f += 256) {
        tws[f] = g_twi[f];
        float2 z;
        if (f <= 512) {
            float2 a = s0[f], b = s1[f];
            z = make_float2(a.x - b.y, a.y + b.x);
        } else {
            int m = LFFT - f;
            float2 a = s0[m], b = s1[m];
            z = make_float2(a.x + b.y, -a.y + b.x);
        }
        bufA[f] = z;
    }
    __syncthreads();
    float2* res = fft1024_r4<1>(bufA, bufB, tws);
    float bias0 = cb[r0 % NDIM];
    float bias1 = cb[r1 % NDIM];
    for (int t = tid; t < T1D; t += 256) {
        float2 v = res[t];
        outp[(size_t)r0 * T1D + t] = v.x * (1.f / 1024.f) + bias0;
        outp[(size_t)r1 * T1D + t] = v.y * (1.f / 1024.f) + bias1;
    }
}

// ---------------- launch ----------------
extern "C" void kernel_launch(void* const* d_in, const int* in_sizes, int n_in,
                              void* d_out, int out_size) {
    const float* infeat = (const float*)d_in[0];
    const float* x    = (const float*)d_in[1];
    const float* w1   = (const float*)d_in[2];  const float* b1  = (const float*)d_in[3];
    const float* w11  = (const float*)d_in[4];  const float* b11 = (const float*)d_in[5];
    const float* w2   = (const float*)d_in[6];  const float* b2  = (const float*)d_in[7];
    const float* w22  = (const float*)d_in[8];  const float* b22 = (const float*)d_in[9];
    const float* w3   = (const float*)d_in[10]; const float* b3  = (const float*)d_in[11];
    const float* w33  = (const float*)d_in[12]; const float* b33 = (const float*)d_in[13];
    const float* cw   = (const float*)d_in[14]; const float* cb  = (const float*)d_in[15];
    const int*   week = (const int*)d_in[16];   const int*   hour = (const int*)d_in[17];
    float* outp = (float*)d_out;

    float *buf0, *buf1, *s1, *s2;
    __nv_bfloat16 *ah0, *al0, *ah1, *al1, *wth, *wtl;
    cudaGetSymbolAddress((void**)&buf0, g_buf0);
    cudaGetSymbolAddress((void**)&buf1, g_buf1);
    cudaGetSymbolAddress((void**)&s1,   g_s1);
    cudaGetSymbolAddress((void**)&s2,   g_s2);
    cudaGetSymbolAddress((void**)&ah0,  g_ah0);
    cudaGetSymbolAddress((void**)&al0,  g_al0);
    cudaGetSymbolAddress((void**)&ah1,  g_ah1);
    cudaGetSymbolAddress((void**)&al1,  g_al1);
    cudaGetSymbolAddress((void**)&wth,  g_wth);
    cudaGetSymbolAddress((void**)&wtl,  g_wtl);

    WP4 wpl; GP6 gpl;
    cudaGetSymbolAddress((void**)&wpl.rh, g_wprh);
    cudaGetSymbolAddress((void**)&wpl.rl, g_wprl);
    cudaGetSymbolAddress((void**)&wpl.ih, g_wpih);
    cudaGetSymbolAddress((void**)&wpl.il, g_wpil);
    cudaGetSymbolAddress((void**)&gpl.rh, g_gprh);
    cudaGetSymbolAddress((void**)&gpl.rl, g_gprl);
    cudaGetSymbolAddress((void**)&gpl.ih, g_gpih);
    cudaGetSymbolAddress((void**)&gpl.il, g_gpil);
    cudaGetSymbolAddress((void**)&gpl.nrh, g_gnrh);
    cudaGetSymbolAddress((void**)&gpl.nrl, g_gnrl);

    cudaFuncSetAttribute(gemm_mma, cudaFuncAttributeMaxDynamicSharedMemorySize, MMA_SMEM);
    cudaFuncSetAttribute(fgemm_mma, cudaFuncAttributeMaxDynamicSharedMemorySize, FG_SMEM);

    const int pb = (MROWS * KP + 255) / 256;
    dim3 gG(MROWS / 128, (NDIM + 63) / 64);

    init_tw_kernel<<<2, 512>>>();
    W6 wp; wp.p[0] = w1; wp.p[1] = w11; wp.p[2] = w2; wp.p[3] = w22; wp.p[4] = w3; wp.p[5] = w33;
    wsplit_kernel<<<(6 * KP * KP + 255) / 256, 256>>>(wp);
    gather_split_kernel<<<pb, 256>>>(infeat, x, week, hour);
    fft_w_kernel<<<(NW + 1) / 2, 256>>>(cw);
    wrepack_kernel<<<dim3((NW + 31) / 32, (FREQ + 31) / 32), 256>>>(wpl);
    {
        long long zn = (long long)FREQ * 23399;
        zpadw_kernel<<<(unsigned)((zn + 255) / 256), 256>>>(wpl);
        zpadg_kernel<<<(FREQ * 352 + 255) / 256, 256>>>(gpl);
    }

    const size_t WS = (size_t)KP * KP;
    gemm_mma<<<gG, 256, MMA_SMEM>>>(ah0, al0, wth + 0 * WS, wtl + 0 * WS, s1);
    gemm_mma<<<gG, 256, MMA_SMEM>>>(ah0, al0, wth + 1 * WS, wtl + 1 * WS, s2);
    stencil_split_kernel<<<pb, 256>>>(s1, s2, b1, b11, buf1, ah1, al1);

    gemm_mma<<<gG, 256, MMA_SMEM>>>(ah1, al1, wth + 2 * WS, wtl + 2 * WS, s1);
    gemm_mma<<<gG, 256, MMA_SMEM>>>(ah1, al1, wth + 3 * WS, wtl + 3 * WS, s2);
    stencil_split_kernel<<<pb, 256>>>(s1, s2, b2, b22, buf0, ah0, al0);

    gemm_mma<<<gG, 256, MMA_SMEM>>>(ah0, al0, wth + 4 * WS, wtl + 4 * WS, s1);
    gemm_mma<<<gG, 256, MMA_SMEM>>>(ah0, al0, wth + 5 * WS, wtl + 5 * WS, s2);
    stencil_split_kernel<<<pb, 256>>>(s1, s2, b3, b33, buf1, ah1, al1);

    fft_g_kernel<<<NG / 2, 256>>>(buf1);
    grepack_kernel<<<dim3((NG + 31) / 32, (FREQ + 31) / 32), 256>>>(gpl);
    fgemm_mma<<<dim3(FREQ, OPAD / 64), 256, FG_SMEM>>>(gpl, wpl);
    ifft_kernel<<<NG / 2, 256>>>(cb, outp);
}

// round 17
// speedup vs baseline: 1.1095x; 1.1095x over previous
#include <cuda_runtime.h>
#include <cuda_bf16.h>
#include <stdint.h>
#include <math.h>

#define BATCH 32
#define NDIM  325
#define T1D   288
#define T3D   864
#define TLEN  2016
#define KSZ   577
#define FREQ  513
#define LFFT  1024
#define FEAT  (BATCH*T3D*NDIM)
#define MROWS (BATCH*T3D)
#define KP    384
#define NW    (NDIM*NDIM)
#define NG    (BATCH*NDIM)
#define IPAD  336
#define OPAD  384

// ---------------- static device scratch ----------------
__device__ float  g_buf0[FEAT];
__device__ float  g_buf1[FEAT];
__device__ float  g_s1[FEAT];
__device__ float  g_s2[FEAT];
__device__ __nv_bfloat16 g_ah0[(size_t)MROWS*KP];
__device__ __nv_bfloat16 g_al0[(size_t)MROWS*KP];
__device__ __nv_bfloat16 g_ah1[(size_t)MROWS*KP];
__device__ __nv_bfloat16 g_al1[(size_t)MROWS*KP];
__device__ __nv_bfloat16 g_wth[6*KP*KP];
__device__ __nv_bfloat16 g_wtl[6*KP*KP];
__device__ float2 g_ghat[(size_t)NG*FREQ];
__device__ float2 g_what[(size_t)NW*FREQ];
__device__ float2 g_ohat[(size_t)NG*FREQ];
__device__ float2 g_twf[LFFT];
__device__ float2 g_twi[LFFT];
__device__ __nv_bfloat16 g_wprh[(size_t)FREQ*OPAD*IPAD];
__device__ __nv_bfloat16 g_wprl[(size_t)FREQ*OPAD*IPAD];
__device__ __nv_bfloat16 g_wpih[(size_t)FREQ*OPAD*IPAD];
__device__ __nv_bfloat16 g_wpil[(size_t)FREQ*OPAD*IPAD];
__device__ __nv_bfloat16 g_gprh[(size_t)FREQ*32*IPAD];
__device__ __nv_bfloat16 g_gprl[(size_t)FREQ*32*IPAD];
__device__ __nv_bfloat16 g_gpih[(size_t)FREQ*32*IPAD];
__device__ __nv_bfloat16 g_gpil[(size_t)FREQ*32*IPAD];
__device__ __nv_bfloat16 g_gnrh[(size_t)FREQ*32*IPAD];
__device__ __nv_bfloat16 g_gnrl[(size_t)FREQ*32*IPAD];

struct WP4 { __nv_bfloat16 *rh, *rl, *ih, *il; };
struct GP6 { __nv_bfloat16 *rh, *rl, *ih, *il, *nrh, *nrl; };

// ---------------- cp.async helpers (LDGSTS, sm_80+) ----------------
__device__ __forceinline__ void cp16(void* dst_smem, const void* src) {
    uint32_t d = (uint32_t)__cvta_generic_to_shared(dst_smem);
    asm volatile("cp.async.cg.shared.global [%0], [%1], 16;" :: "r"(d), "l"(src));
}
#define CP_COMMIT() asm volatile("cp.async.commit_group;" ::: "memory")
#define CP_WAIT1()  asm volatile("cp.async.wait_group 1;" ::: "memory")
#define CP_WAIT0()  asm volatile("cp.async.wait_group 0;" ::: "memory")

// ---------------- gather (+bf16 split) ----------------
__global__ void gather_split_kernel(const float* __restrict__ infeat,
                                    const float* __restrict__ x,
                                    const int* __restrict__ week,
                                    const int* __restrict__ hour) {
    int idx = blockIdx.x * blockDim.x + threadIdx.x;
    if (idx >= MROWS * KP) return;
    int d = idx % KP, t = idx / KP;
    int m = t % T3D, b = t / T3D;
    float v = 0.f;
    if (d < NDIM) {
        if (m >= T1D && m < 2 * T1D) {
            v = infeat[(b * NDIM + d) * T1D + (m - T1D)];
        } else {
            int s  = week[b] * T1D + hour[b];
            int tt = (m + s + (TLEN - T1D)) % TLEN;
            v = x[tt * NDIM + d];
        }
    }
    __nv_bfloat16 h = __float2bfloat16(v);
    g_ah0[idx] = h;
    g_al0[idx] = __float2bfloat16(v - __bfloat162float(h));
}

struct W6 { const float* p[6]; };
__global__ void wsplit_kernel(W6 wp) {
    int idx = blockIdx.x * blockDim.x + threadIdx.x;
    if (idx >= 6 * KP * KP) return;
    int g = idx / (KP * KP);
    int r = idx - g * KP * KP;
    int n = r / KP, k = r - n * KP;
    float v = (n < NDIM && k < NDIM) ? wp.p[g][k * NDIM + n] : 0.f;
    __nv_bfloat16 h = __float2bfloat16(v);
    g_wth[idx] = h;
    g_wtl[idx] = __float2bfloat16(v - __bfloat162float(h));
}

// ---------------- split-bf16 mma.sync GEMM, cp.async double-buffered ----------------
#define SMS    72
#define OFF_AH 0
#define OFF_AL (128*SMS*2)
#define OFF_BH (2*128*SMS*2)
#define OFF_BL (2*128*SMS*2 + 64*SMS*2)
#define SSZ    (2*128*SMS*2 + 2*64*SMS*2)   // 55296 per stage
#define MMA_SMEM (2*SSZ)

#define MMA16816(c, a, b) \
    asm volatile("mma.sync.aligned.m16n8k16.row.col.f32.bf16.bf16.f32 " \
        "{%0,%1,%2,%3}, {%4,%5,%6,%7}, {%8,%9}, {%0,%1,%2,%3};" \
        : "+f"((c)[0]), "+f"((c)[1]), "+f"((c)[2]), "+f"((c)[3]) \
        : "r"((a)[0]), "r"((a)[1]), "r"((a)[2]), "r"((a)[3]), "r"((b)[0]), "r"((b)[1]))

__global__ __launch_bounds__(256)
void gemm_mma(const __nv_bfloat16* __restrict__ Ah, const __nv_bfloat16* __restrict__ Al,
              const __nv_bfloat16* __restrict__ Bh, const __nv_bfloat16* __restrict__ Bl,
              float* __restrict__ C) {
    extern __shared__ char smem[];
    int tid = threadIdx.x, wid = tid >> 5, lane = tid & 31;
    int bm = blockIdx.x * 128, n0 = blockIdx.y * 64;
    int wrow = (wid >> 1) * 32, wcol = (wid & 1) * 32;
    int lr = lane >> 2;
    int lc = (lane & 3) * 2;

    auto issue_chunk = [&](int s, int k0) {
        char* base = smem + s * SSZ;
        __nv_bfloat16* dAh = (__nv_bfloat16*)(base + OFF_AH);
        __nv_bfloat16* dAl = (__nv_bfloat16*)(base + OFF_AL);
        __nv_bfloat16* dBh = (__nv_bfloat16*)(base + OFF_BH);
        __nv_bfloat16* dBl = (__nv_bfloat16*)(base + OFF_BL);
        for (int i = tid; i < 1024; i += 256) {
            int r = i >> 3, q = i & 3, half = (i >> 2) & 1;
            int qq = half * 4 + q;
            cp16(dAh + r * SMS + qq * 8, Ah + (size_t)(bm + r) * KP + k0 + qq * 8);
            cp16(dAl + r * SMS + qq * 8, Al + (size_t)(bm + r) * KP + k0 + qq * 8);
        }
        for (int i = tid; i < 512; i += 256) {
            int r = i >> 3, qq = i & 7;
            cp16(dBh + r * SMS + qq * 8, Bh + (size_t)(n0 + r) * KP + k0 + qq * 8);
            cp16(dBl + r * SMS + qq * 8, Bl + (size_t)(n0 + r) * KP + k0 + qq * 8);
        }
    };

    float acc[2][4][4];
#pragma unroll
    for (int mt = 0; mt < 2; mt++)
#pragma unroll
        for (int nt = 0; nt < 4; nt++)
#pragma unroll
            for (int q = 0; q < 4; q++) acc[mt][nt][q] = 0.f;

    issue_chunk(0, 0);
    CP_COMMIT();

    for (int kc = 0; kc < 6; kc++) {
        if (kc + 1 < 6) {
            issue_chunk((kc + 1) & 1, (kc + 1) * 64);
            CP_COMMIT();
            CP_WAIT1();
        } else {
            CP_WAIT0();
        }
        __syncthreads();
        char* base = smem + (kc & 1) * SSZ;
        __nv_bfloat16* sAh = (__nv_bfloat16*)(base + OFF_AH);
        __nv_bfloat16* sAl = (__nv_bfloat16*)(base + OFF_AL);
        __nv_bfloat16* sBh = (__nv_bfloat16*)(base + OFF_BH);
        __nv_bfloat16* sBl = (__nv_bfloat16*)(base + OFF_BL);

#pragma unroll
        for (int ks = 0; ks < 4; ks++) {
            int kk = ks * 16;
            uint32_t ah[2][4], al[2][4], bh[4][2], bl[4][2];
#pragma unroll
            for (int mt = 0; mt < 2; mt++) {
                int r = wrow + mt * 16 + lr;
                ah[mt][0] = *(const uint32_t*)(sAh + r * SMS + kk + lc);
                ah[mt][1] = *(const uint32_t*)(sAh + (r + 8) * SMS + kk + lc);
                ah[mt][2] = *(const uint32_t*)(sAh + r * SMS + kk + lc + 8);
                ah[mt][3] = *(const uint32_t*)(sAh + (r + 8) * SMS + kk + lc + 8);
                al[mt][0] = *(const uint32_t*)(sAl + r * SMS + kk + lc);
                al[mt][1] = *(const uint32_t*)(sAl + (r + 8) * SMS + kk + lc);
                al[mt][2] = *(const uint32_t*)(sAl + r * SMS + kk + lc + 8);
                al[mt][3] = *(const uint32_t*)(sAl + (r + 8) * SMS + kk + lc + 8);
            }
#pragma unroll
            for (int nt = 0; nt < 4; nt++) {
                int n = wcol + nt * 8 + lr;
                bh[nt][0] = *(const uint32_t*)(sBh + n * SMS + kk + lc);
                bh[nt][1] = *(const uint32_t*)(sBh + n * SMS + kk + lc + 8);
                bl[nt][0] = *(const uint32_t*)(sBl + n * SMS + kk + lc);
                bl[nt][1] = *(const uint32_t*)(sBl + n * SMS + kk + lc + 8);
            }
#pragma unroll
            for (int mt = 0; mt < 2; mt++)
#pragma unroll
                for (int nt = 0; nt < 4; nt++) {
                    MMA16816(acc[mt][nt], ah[mt], bh[nt]);
                    MMA16816(acc[mt][nt], ah[mt], bl[nt]);
                    MMA16816(acc[mt][nt], al[mt], bh[nt]);
                }
        }
        __syncthreads();
    }

#pragma unroll
    for (int mt = 0; mt < 2; mt++) {
        size_t row = (size_t)bm + wrow + mt * 16 + lr;
#pragma unroll
        for (int nt = 0; nt < 4; nt++) {
            int col = n0 + wcol + nt * 8 + lc;
            if (col < NDIM)     C[row * NDIM + col]           = acc[mt][nt][0];
            if (col + 1 < NDIM) C[row * NDIM + col + 1]       = acc[mt][nt][1];
            if (col < NDIM)     C[(row + 8) * NDIM + col]     = acc[mt][nt][2];
            if (col + 1 < NDIM) C[(row + 8) * NDIM + col + 1] = acc[mt][nt][3];
        }
    }
}

// ---------------- banded-A stencil + gate (+bf16 split) ----------------
__global__ void stencil_split_kernel(const float* __restrict__ S1, const float* __restrict__ S2,
                                     const float* __restrict__ bt, const float* __restrict__ bs,
                                     float* __restrict__ outp,
                                     __nv_bfloat16* __restrict__ oh, __nv_bfloat16* __restrict__ ol) {
    int idx = blockIdx.x * blockDim.x + threadIdx.x;
    if (idx >= MROWS * KP) return;
    int o = idx % KP, bm = idx / KP;
    float val = 0.f;
    if (o < NDIM) {
        int m = bm % T3D;
        size_t base = (size_t)(bm - m) * NDIM + o;
        float dm = rsqrtf((float)(1 + min(m, 3) + min(T3D - 1 - m, 3)));
        int lo = (m > 3) ? m - 3 : 0;
        int hi = (m < T3D - 4) ? m + 3 : T3D - 1;
        float s1 = 0.f, s2 = 0.f;
        for (int n = lo; n <= hi; n++) {
            float dn = rsqrtf((float)(1 + min(n, 3) + min(T3D - 1 - n, 3)));
            float w = dm * dn;
            s1 += w * S1[base + (size_t)n * NDIM];
            s2 += w * S2[base + (size_t)n * NDIM];
        }
        float gv = tanhf(s1 + bt[o]);
        float sv = 1.f / (1.f + expf(-(s2 + bs[o])));
        val = gv * sv;
        outp[(size_t)bm * NDIM + o] = val;
    }
    __nv_bfloat16 h = __float2bfloat16(val);
    oh[idx] = h;
    ol[idx] = __float2bfloat16(val - __bfloat162float(h));
}

// ---------------- FFT: radix-4 Stockham, real-pair packed ----------------
__global__ void init_tw_kernel() {
    int idx = blockIdx.x * blockDim.x + threadIdx.x;
    if (idx >= LFFT) return;
    if (idx == 0) { g_twf[0] = make_float2(1.f,0.f); g_twi[0] = make_float2(1.f,0.f); return; }
    int Ns = 1 << (31 - __clz(idx));
    float ang = 3.14159265358979323846f * (float)(idx - Ns) / (float)Ns;
    float s, c; sincosf(ang, &s, &c);
    g_twf[idx] = make_float2(c, -s);
    g_twi[idx] = make_float2(c,  s);
}

__device__ __forceinline__ float2 cmul(float2 a, float2 b) {
    return make_float2(a.x*b.x - a.y*b.y, a.x*b.y + a.y*b.x);
}

template<int INV>
__device__ __forceinline__ float2* fft1024_r4(float2* a, float2* b, const float2* tw) {
    int tid = threadIdx.x;
    float2 *src = a, *dst = b;
#pragma unroll
    for (int Ns = 1; Ns < LFFT; Ns <<= 2) {
        int r = tid & (Ns - 1);
        float2 a0 = src[tid];
        float2 a1 = src[tid + 256];
        float2 a2 = src[tid + 512];
        float2 a3 = src[tid + 768];
        float2 w1 = tw[2 * Ns + r];
        float2 w2 = tw[Ns + r];
        float2 w3 = cmul(w1, w2);
        a1 = cmul(a1, w1);
        a2 = cmul(a2, w2);
        a3 = cmul(a3, w3);
        float2 s0 = make_float2(a0.x + a2.x, a0.y + a2.y);
        float2 d0 = make_float2(a0.x - a2.x, a0.y - a2.y);
        float2 s1 = make_float2(a1.x + a3.x, a1.y + a3.y);
        float2 d1 = make_float2(a1.x - a3.x, a1.y - a3.y);
        float2 b0 = make_float2(s0.x + s1.x, s0.y + s1.y);
        float2 b2 = make_float2(s0.x - s1.x, s0.y - s1.y);
        float2 b1, b3;
        if (INV == 0) {
            b1 = make_float2(d0.x + d1.y, d0.y - d1.x);
            b3 = make_float2(d0.x - d1.y, d0.y + d1.x);
        } else {
            b1 = make_float2(d0.x - d1.y, d0.y + d1.x);
            b3 = make_float2(d0.x + d1.y, d0.y - d1.x);
        }
        int oi = ((tid - r) << 2) + r;
        dst[oi]          = b0;
        dst[oi + Ns]     = b1;
        dst[oi + 2*Ns]   = b2;
        dst[oi + 3*Ns]   = b3;
        __syncthreads();
        float2* t2 = src; src = dst; dst = t2;
    }
    return src;
}

__global__ __launch_bounds__(256)
void fft_w_kernel(const float* __restrict__ cw) {
    __shared__ float2 bufA[LFFT], bufB[LFFT], tws[LFFT];
    int tid = threadIdx.x;
    int r0 = blockIdx.x * 2, r1 = r0 + 1;
    bool has1 = (r1 < NW);
    const float* s0 = cw + (size_t)r0 * KSZ;
    const float* s1 = cw + (size_t)r1 * KSZ;
    for (int t = tid; t < LFFT; t += 256) {
        tws[t] = g_twf[t];
        float v0 = (t < KSZ) ? s0[t] : 0.f;
        float v1 = (has1 && t < KSZ) ? s1[t] : 0.f;
        bufA[t] = make_float2(v0, v1);
    }
    __syncthreads();
    float2* res = fft1024_r4<0>(bufA, bufB, tws);
    float2* d0 = g_what + (size_t)r0 * FREQ;
    float2* d1 = g_what + (size_t)r1 * FREQ;
    for (int f = tid; f <= 512; f += 256) {
        int m = (LFFT - f) & (LFFT - 1);
        float2 zf = res[f], zm = res[m];
        d0[f] = make_float2(0.5f * (zf.x + zm.x), 0.5f * (zf.y - zm.y));
        if (has1) d1[f] = make_float2(0.5f * (zf.y + zm.y), -0.5f * (zf.x - zm.x));
    }
}

__global__ __launch_bounds__(256)
void fft_g_kernel(const float* __restrict__ G) {
    __shared__ float2 bufA[LFFT], bufB[LFFT], tws[LFFT];
    int tid = threadIdx.x;
    int r0 = blockIdx.x * 2, r1 = r0 + 1;
    int b0 = r0 / NDIM, i0 = r0 % NDIM;
    int b1 = r1 / NDIM, i1 = r1 % NDIM;
    const float* s0 = G + (size_t)b0 * T3D * NDIM + i0;
    const float* s1 = G + (size_t)b1 * T3D * NDIM + i1;
    for (int t = tid; t < LFFT; t += 256) {
        tws[t] = g_twf[t];
        float v0 = (t < T3D) ? s0[(size_t)t * NDIM] : 0.f;
        float v1 = (t < T3D) ? s1[(size_t)t * NDIM] : 0.f;
        bufA[t] = make_float2(v0, v1);
    }
    __syncthreads();
    float2* res = fft1024_r4<0>(bufA, bufB, tws);
    float2* d0 = g_ghat + (size_t)r0 * FREQ;
    float2* d1 = g_ghat + (size_t)r1 * FREQ;
    for (int f = tid; f <= 512; f += 256) {
        int m = (LFFT - f) & (LFFT - 1);
        float2 zf = res[f], zm = res[m];
        d0[f] = make_float2(0.5f * (zf.x + zm.x), 0.5f * (zf.y - zm.y));
        d1[f] = make_float2(0.5f * (zf.y + zm.y), -0.5f * (zf.x - zm.x));
    }
}

// ---------------- repack What/Ghat to bf16 split planes [f][o/b][iPad] ----------------
__global__ __launch_bounds__(256)
void wrepack_kernel(WP4 wp) {
    __shared__ float2 t[32][33];
    int oi0 = blockIdx.x * 32, f0 = blockIdx.y * 32;
    int tid = threadIdx.x;
    for (int i = tid; i < 1024; i += 256) {
        int r = i >> 5, c = i & 31;
        int oi = oi0 + r, f = f0 + c;
        float2 v = make_float2(0.f, 0.f);
        if (oi < NW && f < FREQ) v = g_what[(size_t)oi * FREQ + f];
        t[r][c] = v;
    }
    __syncthreads();
    for (int i = tid; i < 1024; i += 256) {
        int fr = i >> 5, c = i & 31;
        int f = f0 + fr, oi = oi0 + c;
        if (f >= FREQ || oi >= NW) continue;
        float2 v = t[c][fr];
        int o = oi / NDIM, ii = oi - o * NDIM;
        size_t ad = (size_t)f * (OPAD * IPAD) + (size_t)o * IPAD + ii;
        __nv_bfloat16 h;
        h = __float2bfloat16(v.x); wp.rh[ad] = h; wp.rl[ad] = __float2bfloat16(v.x - __bfloat162float(h));
        h = __float2bfloat16(v.y); wp.ih[ad] = h; wp.il[ad] = __float2bfloat16(v.y - __bfloat162float(h));
    }
}

__global__ __launch_bounds__(256)
void grepack_kernel(GP6 gp) {
    __shared__ float2 t[32][33];
    int bi0 = blockIdx.x * 32, f0 = blockIdx.y * 32;
    int tid = threadIdx.x;
    for (int i = tid; i < 1024; i += 256) {
        int r = i >> 5, c = i & 31;
        int bi = bi0 + r, f = f0 + c;
        float2 v = make_float2(0.f, 0.f);
        if (bi < NG && f < FREQ) v = g_ghat[(size_t)bi * FREQ + f];
        t[r][c] = v;
    }
    __syncthreads();
    for (int i = tid; i < 1024; i += 256) {
        int fr = i >> 5, c = i & 31;
        int f = f0 + fr, bi = bi0 + c;
        if (f >= FREQ || bi >= NG) continue;
        float2 v = t[c][fr];
        int b = bi / NDIM, ii = bi - b * NDIM;
        size_t ad = (size_t)f * (32 * IPAD) + (size_t)b * IPAD + ii;
        __nv_bfloat16 h, l;
        h = __float2bfloat16(v.x); l = __float2bfloat16(v.x - __bfloat162float(h));
        gp.rh[ad] = h; gp.rl[ad] = l;
        gp.nrh[ad] = __float2bfloat16(-__bfloat162float(h));
        gp.nrl[ad] = __float2bfloat16(-__bfloat162float(l));
        h = __float2bfloat16(v.y); gp.ih[ad] = h; gp.il[ad] = __float2bfloat16(v.y - __bfloat162float(h));
    }
}

// zero the pad regions
__global__ void zpadw_kernel(WP4 wp) {
    long long idx = (long long)blockIdx.x * blockDim.x + threadIdx.x;
    const int PER_F = 59 * 336 + 325 * 11;
    if (idx >= (long long)FREQ * PER_F) return;
    int f = (int)(idx / PER_F);
    int rem = (int)(idx % PER_F);
    int o, ii;
    if (rem < 59 * 336) { o = 325 + rem / 336; ii = rem % 336; }
    else { int r2 = rem - 59 * 336; o = r2 / 11; ii = 325 + r2 % 11; }
    size_t ad = (size_t)f * (OPAD * IPAD) + (size_t)o * IPAD + ii;
    __nv_bfloat16 z = __float2bfloat16(0.f);
    wp.rh[ad] = z; wp.rl[ad] = z; wp.ih[ad] = z; wp.il[ad] = z;
}

__global__ void zpadg_kernel(GP6 gp) {
    int idx = blockIdx.x * blockDim.x + threadIdx.x;
    if (idx >= FREQ * 32 * 11) return;
    int f = idx / 352, rem = idx % 352;
    int b = rem / 11, ii = 325 + rem % 11;
    size_t ad = (size_t)f * (32 * IPAD) + (size_t)b * IPAD + ii;
    __nv_bfloat16 z = __float2bfloat16(0.f);
    gp.rh[ad] = z; gp.rl[ad] = z; gp.ih[ad] = z; gp.il[ad] = z; gp.nrh[ad] = z; gp.nrl[ad] = z;
}

// ---------------- tensor-core frequency GEMM, cp.async double-buffered ----------------
#define FG_STAGE 25088                 // bf16 elems per stage (G 10752 + W 14336)
#define FG_SMEM  (2 * FG_STAGE * 2)    // bytes
__global__ __launch_bounds__(256)
void fgemm_mma(GP6 gp, WP4 wpp) {
    extern __shared__ __nv_bfloat16 sm[];
    int tid = threadIdx.x, wid = tid >> 5, lane = tid & 31;
    int f = blockIdx.x, o0 = blockIdx.y * 64;
    int wrow = (wid & 1) * 16, wcol = (wid >> 1) * 16;
    int lr = lane >> 2, lc = (lane & 3) * 2;

    const __nv_bfloat16* gsrc[6] = {gp.rh, gp.rl, gp.ih, gp.il, gp.nrh, gp.nrl};
    const __nv_bfloat16* wsrc[4] = {wpp.rh, wpp.rl, wpp.ih, wpp.il};

    auto issue_chunk = [&](int s, int kc) {
        __nv_bfloat16* base = sm + s * FG_STAGE;
        if (tid < 192) {
            int r = tid / 6, q = tid % 6;
            size_t so = (size_t)f * (32 * IPAD) + (size_t)r * IPAD + kc * 48 + q * 8;
#pragma unroll
            for (int p = 0; p < 6; p++)
                cp16(base + p * 1792 + r * 56 + q * 8, gsrc[p] + so);
        }
        for (int i = tid; i < 384; i += 256) {
            int r = i / 6, q = i % 6;
            size_t so = (size_t)f * (OPAD * IPAD) + (size_t)(o0 + r) * IPAD + kc * 48 + q * 8;
#pragma unroll
            for (int p = 0; p < 4; p++)
                cp16(base + 10752 + p * 3584 + r * 56 + q * 8, wsrc[p] + so);
        }
    };

    float or_[2][4], oi_[2][4];
#pragma unroll
    for (int p = 0; p < 2; p++)
#pragma unroll
        for (int q = 0; q < 4; q++) { or_[p][q] = 0.f; oi_[p][q] = 0.f; }

    issue_chunk(0, 0);
    CP_COMMIT();

    for (int kc = 0; kc < 7; kc++) {
        if (kc + 1 < 7) {
            issue_chunk((kc + 1) & 1, kc + 1);
            CP_COMMIT();
            CP_WAIT1();
        } else {
            CP_WAIT0();
        }
        __syncthreads();
        __nv_bfloat16* base0 = sm + (kc & 1) * FG_STAGE;

#pragma unroll
        for (int ks = 0; ks < 3; ks++) {
            int kk = ks * 16;
            uint32_t a[6][4];
#pragma unroll
            for (int p = 0; p < 6; p++) {
                const __nv_bfloat16* base = base0 + p * 1792;
                int r = wrow + lr;
                a[p][0] = *(const uint32_t*)(base + r * 56 + kk + lc);
                a[p][1] = *(const uint32_t*)(base + (r + 8) * 56 + kk + lc);
                a[p][2] = *(const uint32_t*)(base + r * 56 + kk + lc + 8);
                a[p][3] = *(const uint32_t*)(base + (r + 8) * 56 + kk + lc + 8);
            }
            uint32_t bf[4][2][2];
#pragma unroll
            for (int p = 0; p < 4; p++)
#pragma unroll
                for (int np = 0; np < 2; np++) {
                    const __nv_bfloat16* base = base0 + 10752 + p * 3584;
                    int n = wcol + np * 8 + lr;
                    bf[p][np][0] = *(const uint32_t*)(base + n * 56 + kk + lc);
                    bf[p][np][1] = *(const uint32_t*)(base + n * 56 + kk + lc + 8);
                }
#pragma unroll
            for (int np = 0; np < 2; np++) {
                MMA16816(or_[np], a[0], bf[0][np]);
                MMA16816(or_[np], a[0], bf[1][np]);
                MMA16816(or_[np], a[1], bf[0][np]);
                MMA16816(or_[np], a[2], bf[2][np]);
                MMA16816(or_[np], a[2], bf[3][np]);
                MMA16816(or_[np], a[3], bf[2][np]);
                MMA16816(oi_[np], a[2], bf[0][np]);
                MMA16816(oi_[np], a[2], bf[1][np]);
                MMA16816(oi_[np], a[3], bf[0][np]);
                MMA16816(oi_[np], a[4], bf[2][np]);
                MMA16816(oi_[np], a[4], bf[3][np]);
                MMA16816(oi_[np], a[5], bf[2][np]);
            }
        }
        __syncthreads();
    }

    int b = wrow + lr;
#pragma unroll
    for (int np = 0; np < 2; np++) {
        int o = o0 + wcol + np * 8 + lc;
        if (o < NDIM) {
            g_ohat[((size_t)b * NDIM + o) * FREQ + f]       = make_float2(or_[np][0], oi_[np][0]);
            g_ohat[((size_t)(b + 8) * NDIM + o) * FREQ + f] = make_float2(or_[np][2], oi_[np][2]);
        }
        if (o + 1 < NDIM) {
            g_ohat[((size_t)b * NDIM + o + 1) * FREQ + f]       = make_float2(or_[np][1], oi_[np][1]);
            g_ohat[((size_t)(b + 8) * NDIM + o + 1) * FREQ + f] = make_float2(or_[np][3], oi_[np][3]);
        }
    }
}

// Inverse: two output rows per block.
__global__ __launch_bounds__(256)
void ifft_kernel(const float* __restrict__ cb, float* __restrict__ outp) {
    __shared__ float2 bufA[LFFT], bufB[LFFT], tws[LFFT];
    int tid = threadIdx.x;
    int r0 = blockIdx.x * 2, r1 = r0 + 1;
    const float2* s0 = g_ohat + (size_t)r0 * FREQ;
    const float2* s1 = g_ohat + (size_t)r1 * FREQ;
    for (int f = tid; f < LFFT; f += 256) {
        tws[f] = g_twi[f];
        float2 z;
        if (f <= 512) {
            float2 a = s0[f], b = s1[f];
            z = make_float2(a.x - b.y, a.y + b.x);
        } else {
            int m = LFFT - f;
            float2 a = s0[m], b = s1[m];
            z = make_float2(a.x + b.y, -a.y + b.x);
        }
        bufA[f] = z;
    }
    __syncthreads();
    float2* res = fft1024_r4<1>(bufA, bufB, tws);
    float bias0 = cb[r0 % NDIM];
    float bias1 = cb[r1 % NDIM];
    for (int t = tid; t < T1D; t += 256) {
        float2 v = res[t];
        outp[(size_t)r0 * T1D + t] = v.x * (1.f / 1024.f) + bias0;
        outp[(size_t)r1 * T1D + t] = v.y * (1.f / 1024.f) + bias1;
    }
}

// ---------------- launch ----------------
extern "C" void kernel_launch(void* const* d_in, const int* in_sizes, int n_in,
                              void* d_out, int out_size) {
    const float* infeat = (const float*)d_in[0];
    const float* x    = (const float*)d_in[1];
    const float* w1   = (const float*)d_in[2];  const float* b1  = (const float*)d_in[3];
    const float* w11  = (const float*)d_in[4];  const float* b11 = (const float*)d_in[5];
    const float* w2   = (const float*)d_in[6];  const float* b2  = (const float*)d_in[7];
    const float* w22  = (const float*)d_in[8];  const float* b22 = (const float*)d_in[9];
    const float* w3   = (const float*)d_in[10]; const float* b3  = (const float*)d_in[11];
    const float* w33  = (const float*)d_in[12]; const float* b33 = (const float*)d_in[13];
    const float* cw   = (const float*)d_in[14]; const float* cb  = (const float*)d_in[15];
    const int*   week = (const int*)d_in[16];   const int*   hour = (const int*)d_in[17];
    float* outp = (float*)d_out;

    float *buf0, *buf1, *s1, *s2;
    __nv_bfloat16 *ah0, *al0, *ah1, *al1, *wth, *wtl;
    cudaGetSymbolAddress((void**)&buf0, g_buf0);
    cudaGetSymbolAddress((void**)&buf1, g_buf1);
    cudaGetSymbolAddress((void**)&s1,   g_s1);
    cudaGetSymbolAddress((void**)&s2,   g_s2);
    cudaGetSymbolAddress((void**)&ah0,  g_ah0);
    cudaGetSymbolAddress((void**)&al0,  g_al0);
    cudaGetSymbolAddress((void**)&ah1,  g_ah1);
    cudaGetSymbolAddress((void**)&al1,  g_al1);
    cudaGetSymbolAddress((void**)&wth,  g_wth);
    cudaGetSymbolAddress((void**)&wtl,  g_wtl);

    WP4 wpl; GP6 gpl;
    cudaGetSymbolAddress((void**)&wpl.rh, g_wprh);
    cudaGetSymbolAddress((void**)&wpl.rl, g_wprl);
    cudaGetSymbolAddress((void**)&wpl.ih, g_wpih);
    cudaGetSymbolAddress((void**)&wpl.il, g_wpil);
    cudaGetSymbolAddress((void**)&gpl.rh, g_gprh);
    cudaGetSymbolAddress((void**)&gpl.rl, g_gprl);
    cudaGetSymbolAddress((void**)&gpl.ih, g_gpih);
    cudaGetSymbolAddress((void**)&gpl.il, g_gpil);
    cudaGetSymbolAddress((void**)&gpl.nrh, g_gnrh);
    cudaGetSymbolAddress((void**)&gpl.nrl, g_gnrl);

    cudaFuncSetAttribute(gemm_mma, cudaFuncAttributeMaxDynamicSharedMemorySize, MMA_SMEM);
    cudaFuncSetAttribute(fgemm_mma, cudaFuncAttributeMaxDynamicSharedMemorySize, FG_SMEM);

    const int pb = (MROWS * KP + 255) / 256;
    dim3 gG(MROWS / 128, (NDIM + 63) / 64);

    init_tw_kernel<<<2, 512>>>();
    W6 wp; wp.p[0] = w1; wp.p[1] = w11; wp.p[2] = w2; wp.p[3] = w22; wp.p[4] = w3; wp.p[5] = w33;
    wsplit_kernel<<<(6 * KP * KP + 255) / 256, 256>>>(wp);
    gather_split_kernel<<<pb, 256>>>(infeat, x, week, hour);
    fft_w_kernel<<<(NW + 1) / 2, 256>>>(cw);
    wrepack_kernel<<<dim3((NW + 31) / 32, (FREQ + 31) / 32), 256>>>(wpl);
    {
        long long zn = (long long)FREQ * 23399;
        zpadw_kernel<<<(unsigned)((zn + 255) / 256), 256>>>(wpl);
        zpadg_kernel<<<(FREQ * 352 + 255) / 256, 256>>>(gpl);
    }

    const size_t WS = (size_t)KP * KP;
    gemm_mma<<<gG, 256, MMA_SMEM>>>(ah0, al0, wth + 0 * WS, wtl + 0 * WS, s1);
    gemm_mma<<<gG, 256, MMA_SMEM>>>(ah0, al0, wth + 1 * WS, wtl + 1 * WS, s2);
    stencil_split_kernel<<<pb, 256>>>(s1, s2, b1, b11, buf1, ah1, al1);

    gemm_mma<<<gG, 256, MMA_SMEM>>>(ah1, al1, wth + 2 * WS, wtl + 2 * WS, s1);
    gemm_mma<<<gG, 256, MMA_SMEM>>>(ah1, al1, wth + 3 * WS, wtl + 3 * WS, s2);
    stencil_split_kernel<<<pb, 256>>>(s1, s2, b2, b22, buf0, ah0, al0);

    gemm_mma<<<gG, 256, MMA_SMEM>>>(ah0, al0, wth + 4 * WS, wtl + 4 * WS, s1);
    gemm_mma<<<gG, 256, MMA_SMEM>>>(ah0, al0, wth + 5 * WS, wtl + 5 * WS, s2);
    stencil_split_kernel<<<pb, 256>>>(s1, s2, b3, b33, buf1, ah1, al1);

    fft_g_kernel<<<NG / 2, 256>>>(buf1);
    grepack_kernel<<<dim3((NG + 31) / 32, (FREQ + 31) / 32), 256>>>(gpl);
    fgemm_mma<<<dim3(FREQ, OPAD / 64), 256, FG_SMEM>>>(gpl, wpl);
    ifft_kernel<<<NG / 2, 256>>>(cb, outp);
}